// round 9
// baseline (speedup 1.0000x reference)
#include <cuda_runtime.h>
#include <cuda_bf16.h>
#include <cstdint>

#define NATOMS 10000
#define NNBH   48
#define NIN    128
#define NF     128
#define NG     25
#define RCUT   5.0f
#define LN2F   0.69314718055994531f

typedef unsigned long long u64;

// ---------------- device scratch (allocation-free rule) ----------------
__device__ __align__(16) float g_ybuf[NATOMS * NF];
__device__ __align__(16) float g_acc [NATOMS * NF];
// W2 fragments: hi at u32[0,8192), lo at u32[8192,16384).
__device__ __align__(16) uint32_t g_W2pk[16384];

__device__ __forceinline__ float sspf(float v) {
    float e  = __expf(-fabsf(v));
    float sp = fmaxf(v, 0.0f) + __logf(1.0f + e);
    return sp - LN2F;
}

__device__ __forceinline__ u64 pk2(float lo, float hi) {
    u64 r; asm("mov.b64 %0, {%1, %2};" : "=l"(r) : "f"(lo), "f"(hi)); return r;
}
__device__ __forceinline__ void ffma2(u64& d, u64 a, u64 b) {
    asm("fma.rn.f32x2 %0, %1, %2, %0;" : "+l"(d) : "l"(a), "l"(b));
}
__device__ __forceinline__ float2 up2(u64 v) {
    float2 f; asm("mov.b64 {%0, %1}, %2;" : "=f"(f.x), "=f"(f.y) : "l"(v)); return f;
}
__device__ __forceinline__ void bfsplit(float v, unsigned short& hi, unsigned short& lo) {
    __nv_bfloat16 h = __float2bfloat16(v);
    float hf = __bfloat162float(h);
    __nv_bfloat16 l = __float2bfloat16(v - hf);
    hi = __bfloat16_as_ushort(h);
    lo = __bfloat16_as_ushort(l);
}
__device__ __forceinline__ uint32_t packu16(unsigned short a, unsigned short b) {
    return (uint32_t)a | ((uint32_t)b << 16);
}
__device__ __forceinline__ void mma16816(float c[4], const uint32_t a[4],
                                         uint32_t b0, uint32_t b1) {
    asm volatile(
        "mma.sync.aligned.m16n8k16.row.col.f32.bf16.bf16.f32 "
        "{%0,%1,%2,%3}, {%4,%5,%6,%7}, {%8,%9}, {%0,%1,%2,%3};"
        : "+f"(c[0]), "+f"(c[1]), "+f"(c[2]), "+f"(c[3])
        : "r"(a[0]), "r"(a[1]), "r"(a[2]), "r"(a[3]), "r"(b0), "r"(b1));
}
__device__ __forceinline__ uint32_t smem_u32(const void* p) {
    uint32_t a;
    asm("{ .reg .u64 t; cvta.to.shared.u64 t, %1; cvt.u32.u64 %0, t; }" : "=r"(a) : "l"(p));
    return a;
}
__device__ __forceinline__ void bar_sync(int b, int n) {
    asm volatile("bar.sync %0, %1;" :: "r"(b), "r"(n) : "memory");
}
__device__ __forceinline__ void bar_arrive(int b, int n) {
    asm volatile("bar.arrive %0, %1;" :: "r"(b), "r"(n) : "memory");
}

// ---------------------------------------------------------------------------
// Kernel A/C: 64x128 tile GEMM, depth 128, micro-tile 4x8, 256 threads, f32x2.
// ---------------------------------------------------------------------------
__global__ __launch_bounds__(256) void gemm128_kernel(
    const float* __restrict__ X, const float* __restrict__ W,
    const float* __restrict__ bias, float* __restrict__ out, int mode)
{
    extern __shared__ float smem[];
    float* sW = smem;
    float* sX = smem + 16384;

    int tid = threadIdx.x;
    const float4* Wv = (const float4*)W;
    float4* sWv = (float4*)sW;
    #pragma unroll
    for (int i = 0; i < 16; i++) sWv[tid + i * 256] = Wv[tid + i * 256];

    int row0 = blockIdx.x * 64;
    const float4* Xv = (const float4*)X;
    float4* sXv = (float4*)sX;
    #pragma unroll
    for (int i = 0; i < 8; i++) {
        int idx = tid + i * 256;
        int r = idx >> 5, c4 = idx & 31;
        float4 v = make_float4(0.f, 0.f, 0.f, 0.f);
        if (row0 + r < NATOMS) v = Xv[(size_t)(row0 + r) * 32 + c4];
        sXv[idx] = v;
    }
    __syncthreads();

    int tr = tid >> 4, tc = tid & 15;
    int r0 = tr * 4, c0 = tc * 8;

    u64 acc[4][4];
    #pragma unroll
    for (int i = 0; i < 4; i++)
        #pragma unroll
        for (int p = 0; p < 4; p++) acc[i][p] = 0ull;

    #pragma unroll 2
    for (int j = 0; j < NIN; j += 4) {
        float4 a0 = *(float4*)&sX[(r0 + 0) * NIN + j];
        float4 a1 = *(float4*)&sX[(r0 + 1) * NIN + j];
        float4 a2 = *(float4*)&sX[(r0 + 2) * NIN + j];
        float4 a3 = *(float4*)&sX[(r0 + 3) * NIN + j];
        const float* af0 = (const float*)&a0;
        const float* af1 = (const float*)&a1;
        const float* af2 = (const float*)&a2;
        const float* af3 = (const float*)&a3;
        #pragma unroll
        for (int jj = 0; jj < 4; jj++) {
            ulonglong2 w0 = *(ulonglong2*)&sW[(j + jj) * NF + c0];
            ulonglong2 w1 = *(ulonglong2*)&sW[(j + jj) * NF + c0 + 4];
            u64 p0 = pk2(af0[jj], af0[jj]);
            u64 p1 = pk2(af1[jj], af1[jj]);
            u64 p2 = pk2(af2[jj], af2[jj]);
            u64 p3 = pk2(af3[jj], af3[jj]);
            ffma2(acc[0][0], p0, w0.x); ffma2(acc[0][1], p0, w0.y);
            ffma2(acc[0][2], p0, w1.x); ffma2(acc[0][3], p0, w1.y);
            ffma2(acc[1][0], p1, w0.x); ffma2(acc[1][1], p1, w0.y);
            ffma2(acc[1][2], p1, w1.x); ffma2(acc[1][3], p1, w1.y);
            ffma2(acc[2][0], p2, w0.x); ffma2(acc[2][1], p2, w0.y);
            ffma2(acc[2][2], p2, w1.x); ffma2(acc[2][3], p2, w1.y);
            ffma2(acc[3][0], p3, w0.x); ffma2(acc[3][1], p3, w0.y);
            ffma2(acc[3][2], p3, w1.x); ffma2(acc[3][3], p3, w1.y);
        }
    }

    float bb[8];
    if (mode == 1) {
        #pragma unroll
        for (int c = 0; c < 8; c++) bb[c] = bias[c0 + c];
    }
    #pragma unroll
    for (int i = 0; i < 4; i++) {
        int r = row0 + r0 + i;
        if (r < NATOMS) {
            float o[8];
            #pragma unroll
            for (int p = 0; p < 4; p++) {
                float2 f = up2(acc[i][p]);
                o[2 * p] = f.x; o[2 * p + 1] = f.y;
            }
            if (mode == 1) {
                #pragma unroll
                for (int c = 0; c < 8; c++) o[c] = sspf(o[c] + bb[c]);
            }
            *(float4*)&out[(size_t)r * NF + c0]     = make_float4(o[0], o[1], o[2], o[3]);
            *(float4*)&out[(size_t)r * NF + c0 + 4] = make_float4(o[4], o[5], o[6], o[7]);
        }
    }
}

// ---------------------------------------------------------------------------
// prepack: split W2 -> bf16 hi/lo in m16n8k16 B-fragment layout (validated).
// ---------------------------------------------------------------------------
__global__ void prepack_kernel(const float* __restrict__ W2)
{
    int idx = blockIdx.x * 256 + threadIdx.x;
    if (idx >= 4096) return;
    int kt = idx >> 9, s = (idx >> 7) & 3, n = idx & 127;
    int k = kt * 16 + 2 * s;
    float e0 = W2[(k + 0) * NF + n], e1 = W2[(k + 1) * NF + n];
    float e8 = W2[(k + 8) * NF + n], e9 = W2[(k + 9) * NF + n];
    unsigned short h0, l0, h1, l1, h8, l8, h9, l9;
    bfsplit(e0, h0, l0); bfsplit(e1, h1, l1);
    bfsplit(e8, h8, l8); bfsplit(e9, h9, l9);
    int slot = kt * 512 + n * 4 + s;
    g_W2pk[slot * 2 + 0]        = packu16(h0, h1);
    g_W2pk[slot * 2 + 1]        = packu16(h8, h9);
    g_W2pk[8192 + slot * 2 + 0] = packu16(l0, l1);
    g_W2pk[8192 + slot * 2 + 1] = packu16(l8, l9);
}

// ---------------------------------------------------------------------------
// Kernel B: warp-specialized producer/consumer, double-buffered H, 2 CTAs/SM.
//   warps 0-3  (128 thr): stage + GEMM1 (FFMA2) -> ssp -> bf16 split -> H[buf]
//   warps 4-11 (256 thr): ldmatrix + 3-term split-bf16 mma + fused epilogue
// Named barriers: 1,2 = FULL[0..1]; 3,4 = EMPTY[0..1]; 5 = producer-internal.
// ---------------------------------------------------------------------------
#define APB 8
#define NTH 384

struct SmemWS {
    float    W1[NG * NF];                          // 12800 B
    __align__(16) uint32_t Wlo[8192];              // 32768 B
    __align__(16) __nv_bfloat16 Hhi[2][NNBH * NF]; // 2*12288 B
    __align__(16) __nv_bfloat16 Hlo[2][NNBH * NF]; // 2*12288 B
    __align__(16) float G[2][NNBH * NG];           // 2*4800 B
    float    CM[2][NNBH];
    int      Idx[2][NNBH];
};                                                 // 105088 B

__global__ __launch_bounds__(NTH, 2) void cfconv_ws_kernel(
    const float* __restrict__ dR,   const float* __restrict__ dRe,
    const float* __restrict__ pmask,const int*   __restrict__ nbr,
    const float* __restrict__ W1,   const float* __restrict__ b1,
    const float* __restrict__ b2)
{
    extern __shared__ __align__(16) char smraw[];
    SmemWS* sm = (SmemWS*)smraw;

    int tid  = threadIdx.x;
    int lane = tid & 31, w = tid >> 5;

    // one-time loads by all 384 threads
    for (int i = tid; i < 800; i += NTH)
        ((uint4*)sm->W1)[i] = ((const uint4*)W1)[i];
    for (int i = tid; i < 2048; i += NTH)
        ((uint4*)sm->Wlo)[i] = ((const uint4*)(g_W2pk + 8192))[i];
    __syncthreads();

    size_t base = (size_t)blockIdx.x * APB;

    if (w < 4) {
        // ======================= PRODUCERS (128 threads) ====================
        int pt = tid;                // 0..127
        int tc = pt >> 3;            // 0..15 -> cols tc*8..tc*8+7
        int rw = pt & 7;             // row group
        u64 b1p[4];
        #pragma unroll
        for (int p = 0; p < 4; p++)
            b1p[p] = pk2(b1[tc * 8 + 2 * p], b1[tc * 8 + 2 * p + 1]);

        #pragma unroll 1
        for (int it = 0; it < APB; it++) {
            int buf = it & 1;
            if (it >= 2) bar_sync(3 + buf, NTH);   // EMPTY[buf]

            size_t atom = base + it;
            {
                const uint4* gs = (const uint4*)(dRe + atom * (NNBH * NG));
                uint4* gd = (uint4*)sm->G[buf];
                for (int i = pt; i < 300; i += 128) gd[i] = gs[i];
                if (pt < NNBH) {
                    sm->Idx[buf][pt] = nbr[atom * NNBH + pt];
                    float d = dR[atom * NNBH + pt];
                    sm->CM[buf][pt] = (d <= RCUT ? 1.0f : 0.0f) * pmask[atom * NNBH + pt];
                }
            }
            bar_sync(5, 128);   // producer-internal: G staged

            #pragma unroll
            for (int pass = 0; pass < 2; pass++) {
                int rbase = rw + 24 * pass;
                u64 h[3][4];
                #pragma unroll
                for (int i = 0; i < 3; i++)
                    #pragma unroll
                    for (int p = 0; p < 4; p++) h[i][p] = b1p[p];
                #pragma unroll
                for (int g = 0; g < NG; g++) {
                    float a0 = sm->G[buf][(rbase +  0) * NG + g];
                    float a1 = sm->G[buf][(rbase +  8) * NG + g];
                    float a2 = sm->G[buf][(rbase + 16) * NG + g];
                    const float* wr = &sm->W1[g * NF + tc * 8];
                    ulonglong2 w0 = *(ulonglong2*)(wr);
                    ulonglong2 w1 = *(ulonglong2*)(wr + 4);
                    u64 p0 = pk2(a0, a0), p1 = pk2(a1, a1), p2 = pk2(a2, a2);
                    ffma2(h[0][0], p0, w0.x); ffma2(h[0][1], p0, w0.y);
                    ffma2(h[0][2], p0, w1.x); ffma2(h[0][3], p0, w1.y);
                    ffma2(h[1][0], p1, w0.x); ffma2(h[1][1], p1, w0.y);
                    ffma2(h[1][2], p1, w1.x); ffma2(h[1][3], p1, w1.y);
                    ffma2(h[2][0], p2, w0.x); ffma2(h[2][1], p2, w0.y);
                    ffma2(h[2][2], p2, w1.x); ffma2(h[2][3], p2, w1.y);
                }
                #pragma unroll
                for (int i = 0; i < 3; i++) {
                    int row = rbase + i * 8;
                    uint32_t phi[4], plo[4];
                    #pragma unroll
                    for (int p = 0; p < 4; p++) {
                        float2 f = up2(h[i][p]);
                        float v0 = sspf(f.x), v1 = sspf(f.y);
                        unsigned short hh0, ll0, hh1, ll1;
                        bfsplit(v0, hh0, ll0);
                        bfsplit(v1, hh1, ll1);
                        phi[p] = packu16(hh0, hh1);
                        plo[p] = packu16(ll0, ll1);
                    }
                    int ci = row * 16 + (tc ^ (row & 7));
                    ((uint4*)sm->Hhi[buf])[ci] = make_uint4(phi[0], phi[1], phi[2], phi[3]);
                    ((uint4*)sm->Hlo[buf])[ci] = make_uint4(plo[0], plo[1], plo[2], plo[3]);
                }
            }
            bar_arrive(1 + buf, NTH);   // FULL[buf]
        }
    } else {
        // ======================= CONSUMERS (256 threads) ====================
        int wc = w - 4;                 // 0..7
        int nn = wc * 16;
        int t4 = lane & 3, g4 = lane >> 2;

        uint32_t Whi[2][8][2];
        int fragoff[2];
        #pragma unroll
        for (int nt = 0; nt < 2; nt++) {
            int ncol = nn + nt * 8 + g4;
            fragoff[nt] = ncol * 4 + t4;
            #pragma unroll
            for (int kt = 0; kt < 8; kt++) {
                u64 v = *(const u64*)&g_W2pk[(kt * 512 + fragoff[nt]) * 2];
                Whi[nt][kt][0] = (uint32_t)v;
                Whi[nt][kt][1] = (uint32_t)(v >> 32);
            }
        }
        float2 b2v[2];
        b2v[0] = *(const float2*)&b2[nn + 2 * t4];
        b2v[1] = *(const float2*)&b2[nn + 8 + 2 * t4];

        int q = lane >> 3, rr = lane & 7;
        int lrow = (q & 1) * 8 + rr;
        int qh = q >> 1;
        uint32_t sbhi[2] = { smem_u32(sm->Hhi[0]), smem_u32(sm->Hhi[1]) };
        uint32_t sblo[2] = { smem_u32(sm->Hlo[0]), smem_u32(sm->Hlo[1]) };

        #pragma unroll 1
        for (int it = 0; it < APB; it++) {
            int buf = it & 1;
            bar_sync(1 + buf, NTH);     // FULL[buf]

            size_t atom = base + it;
            float colacc[4] = {0.f, 0.f, 0.f, 0.f};

            #pragma unroll
            for (int mt = 0; mt < 3; mt++) {
                float cA[2][4], cB[2][4];
                #pragma unroll
                for (int nt = 0; nt < 2; nt++)
                    #pragma unroll
                    for (int i = 0; i < 4; i++) { cA[nt][i] = 0.f; cB[nt][i] = 0.f; }

                uint32_t rowoff = (uint32_t)(mt * 16 + lrow) * 256;
                #pragma unroll
                for (int kt = 0; kt < 8; kt++) {
                    uint32_t off = rowoff + (uint32_t)(((kt * 2 + qh) ^ rr) * 16);
                    uint32_t ahi[4], alo[4];
                    asm volatile("ldmatrix.sync.aligned.m8n8.x4.shared.b16 {%0,%1,%2,%3}, [%4];"
                        : "=r"(ahi[0]), "=r"(ahi[1]), "=r"(ahi[2]), "=r"(ahi[3])
                        : "r"(sbhi[buf] + off));
                    asm volatile("ldmatrix.sync.aligned.m8n8.x4.shared.b16 {%0,%1,%2,%3}, [%4];"
                        : "=r"(alo[0]), "=r"(alo[1]), "=r"(alo[2]), "=r"(alo[3])
                        : "r"(sblo[buf] + off));
                    #pragma unroll
                    for (int nt = 0; nt < 2; nt++) {
                        u64 wl = *(const u64*)&sm->Wlo[(kt * 512 + fragoff[nt]) * 2];
                        uint32_t wl0 = (uint32_t)wl, wl1 = (uint32_t)(wl >> 32);
                        mma16816(cA[nt], ahi, Whi[nt][kt][0], Whi[nt][kt][1]);
                        mma16816(cB[nt], ahi, wl0, wl1);
                        mma16816(cB[nt], alo, Whi[nt][kt][0], Whi[nt][kt][1]);
                    }
                }

                int kbase = mt * 16;
                float cm0 = sm->CM[buf][kbase + g4];
                float cm8 = sm->CM[buf][kbase + 8 + g4];
                int n0i = sm->Idx[buf][kbase + g4];
                int n8i = sm->Idx[buf][kbase + 8 + g4];
                #pragma unroll
                for (int nt = 0; nt < 2; nt++) {
                    int coln = nn + nt * 8 + 2 * t4;
                    float2 y0 = *(const float2*)&g_ybuf[(size_t)n0i * NF + coln];
                    float2 y8 = *(const float2*)&g_ybuf[(size_t)n8i * NF + coln];
                    float p0 = cA[nt][0] + cB[nt][0] + b2v[nt].x;
                    float p1 = cA[nt][1] + cB[nt][1] + b2v[nt].y;
                    float p2 = cA[nt][2] + cB[nt][2] + b2v[nt].x;
                    float p3 = cA[nt][3] + cB[nt][3] + b2v[nt].y;
                    colacc[nt * 2 + 0] += cm0 * y0.x * p0 + cm8 * y8.x * p2;
                    colacc[nt * 2 + 1] += cm0 * y0.y * p1 + cm8 * y8.y * p3;
                }
            }

            #pragma unroll
            for (int m = 4; m <= 16; m <<= 1) {
                #pragma unroll
                for (int i = 0; i < 4; i++)
                    colacc[i] += __shfl_xor_sync(0xFFFFFFFF, colacc[i], m);
            }
            if (g4 == 0) {
                *(float2*)&g_acc[atom * NF + nn + 2 * t4]     = make_float2(colacc[0], colacc[1]);
                *(float2*)&g_acc[atom * NF + nn + 8 + 2 * t4] = make_float2(colacc[2], colacc[3]);
            }
            bar_arrive(3 + buf, NTH);   // EMPTY[buf]
        }
    }
}

// ---------------------------------------------------------------------------
extern "C" void kernel_launch(void* const* d_in, const int* in_sizes, int n_in,
                              void* d_out, int out_size)
{
    const float* x       = (const float*)d_in[0];
    const float* dR      = (const float*)d_in[1];
    const float* dRe     = (const float*)d_in[2];
    const float* pmask   = (const float*)d_in[3];
    const int*   nbr     = (const int*)  d_in[4];
    const float* W1      = (const float*)d_in[5];
    const float* b1      = (const float*)d_in[6];
    const float* W2      = (const float*)d_in[7];
    const float* b2      = (const float*)d_in[8];
    const float* W_in2f  = (const float*)d_in[9];
    const float* W_f2out = (const float*)d_in[10];
    const float* b_f2out = (const float*)d_in[11];
    float* out = (float*)d_out;

    const int SMEM_AC = (16384 + 64 * 128) * 4;   // 98304 B
    const int SMEM_B  = (int)sizeof(SmemWS);      // 105088 B

    cudaFuncSetAttribute(gemm128_kernel,   cudaFuncAttributeMaxDynamicSharedMemorySize, SMEM_AC);
    cudaFuncSetAttribute(cfconv_ws_kernel, cudaFuncAttributeMaxDynamicSharedMemorySize, SMEM_B);

    float* ybuf; cudaGetSymbolAddress((void**)&ybuf, g_ybuf);
    float* accb; cudaGetSymbolAddress((void**)&accb, g_acc);

    int gridAC = (NATOMS + 63) / 64;      // 157
    int gridB  = NATOMS / APB;            // 1250

    prepack_kernel<<<16, 256>>>(W2);
    gemm128_kernel<<<gridAC, 256, SMEM_AC>>>(x, W_in2f, nullptr, ybuf, 0);
    cfconv_ws_kernel<<<gridB, NTH, SMEM_B>>>(dR, dRe, pmask, nbr, W1, b1, b2);
    gemm128_kernel<<<gridAC, 256, SMEM_AC>>>(accb, W_f2out, b_f2out, out, 1);
}

// round 10
// speedup vs baseline: 1.6609x; 1.6609x over previous
#include <cuda_runtime.h>
#include <cuda_bf16.h>
#include <cstdint>

#define NATOMS 10000
#define NNBH   48
#define NIN    128
#define NF     128
#define NG     25
#define RCUT   5.0f
#define LN2F   0.69314718055994531f

typedef unsigned long long u64;

// ---------------- device scratch (allocation-free rule) ----------------
__device__ __align__(16) float g_ybuf[NATOMS * NF];
__device__ __align__(16) float g_acc [NATOMS * NF];
// W2 fragments: hi at u32[0,8192), lo at u32[8192,16384).
// u64-slot index: kt*512 + n*4 + s
__device__ __align__(16) uint32_t g_W2pk[16384];
__device__ int g_dummy_sink;

__device__ __forceinline__ float sspf(float v) {
    float e  = __expf(-fabsf(v));
    float sp = fmaxf(v, 0.0f) + __logf(1.0f + e);
    return sp - LN2F;
}

__device__ __forceinline__ u64 pk2(float lo, float hi) {
    u64 r; asm("mov.b64 %0, {%1, %2};" : "=l"(r) : "f"(lo), "f"(hi)); return r;
}
__device__ __forceinline__ void ffma2(u64& d, u64 a, u64 b) {
    asm("fma.rn.f32x2 %0, %1, %2, %0;" : "+l"(d) : "l"(a), "l"(b));
}
__device__ __forceinline__ float2 up2(u64 v) {
    float2 f; asm("mov.b64 {%0, %1}, %2;" : "=f"(f.x), "=f"(f.y) : "l"(v)); return f;
}
__device__ __forceinline__ void bfsplit(float v, unsigned short& hi, unsigned short& lo) {
    __nv_bfloat16 h = __float2bfloat16(v);
    float hf = __bfloat162float(h);
    __nv_bfloat16 l = __float2bfloat16(v - hf);
    hi = __bfloat16_as_ushort(h);
    lo = __bfloat16_as_ushort(l);
}
__device__ __forceinline__ uint32_t packu16(unsigned short a, unsigned short b) {
    return (uint32_t)a | ((uint32_t)b << 16);
}
__device__ __forceinline__ void mma16816(float c[4], const uint32_t a[4],
                                         uint32_t b0, uint32_t b1) {
    asm volatile(
        "mma.sync.aligned.m16n8k16.row.col.f32.bf16.bf16.f32 "
        "{%0,%1,%2,%3}, {%4,%5,%6,%7}, {%8,%9}, {%0,%1,%2,%3};"
        : "+f"(c[0]), "+f"(c[1]), "+f"(c[2]), "+f"(c[3])
        : "r"(a[0]), "r"(a[1]), "r"(a[2]), "r"(a[3]), "r"(b0), "r"(b1));
}
__device__ __forceinline__ uint32_t smem_u32(const void* p) {
    uint32_t a;
    asm("{ .reg .u64 t; cvta.to.shared.u64 t, %1; cvt.u32.u64 %0, t; }" : "=r"(a) : "l"(p));
    return a;
}

// ---------------------------------------------------------------------------
// Kernel A/C: 64x128 tile GEMM, depth 128, micro-tile 4x8, 256 threads, f32x2.
// mode 0 (A): blocks >= 157 instead perform the W2 fragment prepack.
// ---------------------------------------------------------------------------
#define GRID_GEMM 157

__global__ __launch_bounds__(256) void gemm128_kernel(
    const float* __restrict__ X, const float* __restrict__ W,
    const float* __restrict__ bias, float* __restrict__ out, int mode,
    const float* __restrict__ W2)
{
    if (blockIdx.x >= GRID_GEMM) {
        // ---- fused prepack (16 blocks x 256 threads = 4096 work items) ----
        int idx = (blockIdx.x - GRID_GEMM) * 256 + threadIdx.x;
        if (idx < 4096 && W2 != nullptr) {
            int kt = idx >> 9, s = (idx >> 7) & 3, n = idx & 127;
            int k = kt * 16 + 2 * s;
            float e0 = W2[(k + 0) * NF + n], e1 = W2[(k + 1) * NF + n];
            float e8 = W2[(k + 8) * NF + n], e9 = W2[(k + 9) * NF + n];
            unsigned short h0, l0, h1, l1, h8, l8, h9, l9;
            bfsplit(e0, h0, l0); bfsplit(e1, h1, l1);
            bfsplit(e8, h8, l8); bfsplit(e9, h9, l9);
            int slot = kt * 512 + n * 4 + s;
            g_W2pk[slot * 2 + 0]        = packu16(h0, h1);
            g_W2pk[slot * 2 + 1]        = packu16(h8, h9);
            g_W2pk[8192 + slot * 2 + 0] = packu16(l0, l1);
            g_W2pk[8192 + slot * 2 + 1] = packu16(l8, l9);
        }
        return;
    }

    extern __shared__ float smem[];
    float* sW = smem;
    float* sX = smem + 16384;

    int tid = threadIdx.x;
    const float4* Wv = (const float4*)W;
    float4* sWv = (float4*)sW;
    #pragma unroll
    for (int i = 0; i < 16; i++) sWv[tid + i * 256] = Wv[tid + i * 256];

    int row0 = blockIdx.x * 64;
    const float4* Xv = (const float4*)X;
    float4* sXv = (float4*)sX;
    #pragma unroll
    for (int i = 0; i < 8; i++) {
        int idx = tid + i * 256;
        int r = idx >> 5, c4 = idx & 31;
        float4 v = make_float4(0.f, 0.f, 0.f, 0.f);
        if (row0 + r < NATOMS) v = Xv[(size_t)(row0 + r) * 32 + c4];
        sXv[idx] = v;
    }
    __syncthreads();

    int tr = tid >> 4, tc = tid & 15;
    int r0 = tr * 4, c0 = tc * 8;

    u64 acc[4][4];
    #pragma unroll
    for (int i = 0; i < 4; i++)
        #pragma unroll
        for (int p = 0; p < 4; p++) acc[i][p] = 0ull;

    #pragma unroll 2
    for (int j = 0; j < NIN; j += 4) {
        float4 a0 = *(float4*)&sX[(r0 + 0) * NIN + j];
        float4 a1 = *(float4*)&sX[(r0 + 1) * NIN + j];
        float4 a2 = *(float4*)&sX[(r0 + 2) * NIN + j];
        float4 a3 = *(float4*)&sX[(r0 + 3) * NIN + j];
        const float* af0 = (const float*)&a0;
        const float* af1 = (const float*)&a1;
        const float* af2 = (const float*)&a2;
        const float* af3 = (const float*)&a3;
        #pragma unroll
        for (int jj = 0; jj < 4; jj++) {
            ulonglong2 w0 = *(ulonglong2*)&sW[(j + jj) * NF + c0];
            ulonglong2 w1 = *(ulonglong2*)&sW[(j + jj) * NF + c0 + 4];
            u64 p0 = pk2(af0[jj], af0[jj]);
            u64 p1 = pk2(af1[jj], af1[jj]);
            u64 p2 = pk2(af2[jj], af2[jj]);
            u64 p3 = pk2(af3[jj], af3[jj]);
            ffma2(acc[0][0], p0, w0.x); ffma2(acc[0][1], p0, w0.y);
            ffma2(acc[0][2], p0, w1.x); ffma2(acc[0][3], p0, w1.y);
            ffma2(acc[1][0], p1, w0.x); ffma2(acc[1][1], p1, w0.y);
            ffma2(acc[1][2], p1, w1.x); ffma2(acc[1][3], p1, w1.y);
            ffma2(acc[2][0], p2, w0.x); ffma2(acc[2][1], p2, w0.y);
            ffma2(acc[2][2], p2, w1.x); ffma2(acc[2][3], p2, w1.y);
            ffma2(acc[3][0], p3, w0.x); ffma2(acc[3][1], p3, w0.y);
            ffma2(acc[3][2], p3, w1.x); ffma2(acc[3][3], p3, w1.y);
        }
    }

    float bb[8];
    if (mode == 1) {
        #pragma unroll
        for (int c = 0; c < 8; c++) bb[c] = bias[c0 + c];
    }
    #pragma unroll
    for (int i = 0; i < 4; i++) {
        int r = row0 + r0 + i;
        if (r < NATOMS) {
            float o[8];
            #pragma unroll
            for (int p = 0; p < 4; p++) {
                float2 f = up2(acc[i][p]);
                o[2 * p] = f.x; o[2 * p + 1] = f.y;
            }
            if (mode == 1) {
                #pragma unroll
                for (int c = 0; c < 8; c++) o[c] = sspf(o[c] + bb[c]);
            }
            *(float4*)&out[(size_t)r * NF + c0]     = make_float4(o[0], o[1], o[2], o[3]);
            *(float4*)&out[(size_t)r * NF + c0 + 4] = make_float4(o[4], o[5], o[6], o[7]);
        }
    }
}

// trivial tail launch (keeps cfconv at launch position 2 -> ncu captures it)
__global__ void dummy_kernel() {
    if (threadIdx.x == 0 && blockIdx.x == 0) g_dummy_sink = 1;
}

// ---------------------------------------------------------------------------
// Kernel B (fused): GEMM1 (FFMA2, 3 rows jointly) -> ssp -> bf16 split ->
// XOR-swizzled smem H -> ldmatrix + split-bf16 mma GEMM2 (Whi in regs, Wlo
// from smem) -> fused epilogue. 256 threads, 8 atoms/block, 2 CTAs/SM.
// (identical to the R6 404us configuration)
// ---------------------------------------------------------------------------
#define APB 8

struct SmemB {
    float    W1[NG * NF];                        // 12800 B
    __align__(16) uint32_t Wlo[8192];            // 32768 B
    float    G[NNBH * NG];                       // 4800 B
    __align__(16) __nv_bfloat16 Hhi[NNBH * NF];  // 12288 B
    __align__(16) __nv_bfloat16 Hlo[NNBH * NF];  // 12288 B
    float    CM[NNBH];
    int      Idx[NNBH];
};

__global__ __launch_bounds__(256, 2) void cfconv_fused_kernel(
    const float* __restrict__ dR,   const float* __restrict__ dRe,
    const float* __restrict__ pmask,const int*   __restrict__ nbr,
    const float* __restrict__ W1,   const float* __restrict__ b1,
    const float* __restrict__ b2)
{
    extern __shared__ __align__(16) char smraw[];
    SmemB* sm = (SmemB*)smraw;

    int tid  = threadIdx.x;
    int lane = tid & 31, w = tid >> 5;

    for (int i = tid; i < NG * NF; i += 256) sm->W1[i] = W1[i];
    {
        const uint4* src = (const uint4*)(g_W2pk + 8192);
        uint4* dst = (uint4*)sm->Wlo;
        #pragma unroll
        for (int i = 0; i < 8; i++) dst[tid + i * 256] = src[tid + i * 256];
    }

    int nn = w * 16;
    int t4 = lane & 3, g4 = lane >> 2;

    uint32_t Whi[2][8][2];
    int fragoff[2];
    #pragma unroll
    for (int nt = 0; nt < 2; nt++) {
        int ncol = nn + nt * 8 + g4;
        fragoff[nt] = ncol * 4 + t4;
        #pragma unroll
        for (int kt = 0; kt < 8; kt++) {
            u64 v = *(const u64*)&g_W2pk[(kt * 512 + fragoff[nt]) * 2];
            Whi[nt][kt][0] = (uint32_t)v;
            Whi[nt][kt][1] = (uint32_t)(v >> 32);
        }
    }
    float2 b2v[2];
    b2v[0] = *(const float2*)&b2[nn + 2 * t4];
    b2v[1] = *(const float2*)&b2[nn + 8 + 2 * t4];

    int tr = tid >> 4, tc = tid & 15;
    u64 b1p[4];
    #pragma unroll
    for (int p = 0; p < 4; p++)
        b1p[p] = pk2(b1[tc * 8 + 2 * p], b1[tc * 8 + 2 * p + 1]);

    int q = lane >> 3, rr = lane & 7;
    int lrow = (q & 1) * 8 + rr;
    int qh = q >> 1;
    uint32_t sbase_hi = smem_u32(sm->Hhi);
    uint32_t sbase_lo = smem_u32(sm->Hlo);

    #pragma unroll 1
    for (int a = 0; a < APB; a++) {
        int atom = blockIdx.x * APB + a;
        __syncthreads();

        const float* gsrc = dRe + (size_t)atom * (NNBH * NG);
        for (int i = tid; i < NNBH * NG; i += 256) sm->G[i] = gsrc[i];
        if (tid < NNBH) {
            sm->Idx[tid] = nbr[(size_t)atom * NNBH + tid];
            float d = dR[(size_t)atom * NNBH + tid];
            sm->CM[tid] = (d <= RCUT ? 1.0f : 0.0f) * pmask[(size_t)atom * NNBH + tid];
        }
        __syncthreads();

        // --- GEMM1: H = ssp(G @ W1 + b1), 3 rows jointly -> split bf16 ---
        {
            u64 h[3][4];
            #pragma unroll
            for (int i = 0; i < 3; i++)
                #pragma unroll
                for (int p = 0; p < 4; p++) h[i][p] = b1p[p];
            #pragma unroll
            for (int g = 0; g < NG; g++) {
                float a0 = sm->G[(tr +  0) * NG + g];
                float a1 = sm->G[(tr + 16) * NG + g];
                float a2 = sm->G[(tr + 32) * NG + g];
                const float* wr = &sm->W1[g * NF + tc * 8];
                ulonglong2 w0 = *(ulonglong2*)(wr);
                ulonglong2 w1 = *(ulonglong2*)(wr + 4);
                u64 p0 = pk2(a0, a0), p1 = pk2(a1, a1), p2 = pk2(a2, a2);
                ffma2(h[0][0], p0, w0.x); ffma2(h[0][1], p0, w0.y);
                ffma2(h[0][2], p0, w1.x); ffma2(h[0][3], p0, w1.y);
                ffma2(h[1][0], p1, w0.x); ffma2(h[1][1], p1, w0.y);
                ffma2(h[1][2], p1, w1.x); ffma2(h[1][3], p1, w1.y);
                ffma2(h[2][0], p2, w0.x); ffma2(h[2][1], p2, w0.y);
                ffma2(h[2][2], p2, w1.x); ffma2(h[2][3], p2, w1.y);
            }
            #pragma unroll
            for (int i = 0; i < 3; i++) {
                int row = tr + i * 16;
                uint32_t phi[4], plo[4];
                #pragma unroll
                for (int p = 0; p < 4; p++) {
                    float2 f = up2(h[i][p]);
                    float v0 = sspf(f.x), v1 = sspf(f.y);
                    unsigned short hh0, ll0, hh1, ll1;
                    bfsplit(v0, hh0, ll0);
                    bfsplit(v1, hh1, ll1);
                    phi[p] = packu16(hh0, hh1);
                    plo[p] = packu16(ll0, ll1);
                }
                int ci = row * 16 + (tc ^ (row & 7));
                ((uint4*)sm->Hhi)[ci] = make_uint4(phi[0], phi[1], phi[2], phi[3]);
                ((uint4*)sm->Hlo)[ci] = make_uint4(plo[0], plo[1], plo[2], plo[3]);
            }
        }
        __syncthreads();

        // --- GEMM2 (mma) + epilogue ---
        float colacc[4] = {0.f, 0.f, 0.f, 0.f};

        #pragma unroll
        for (int mt = 0; mt < 3; mt++) {
            float cA[2][4], cB[2][4];
            #pragma unroll
            for (int nt = 0; nt < 2; nt++)
                #pragma unroll
                for (int i = 0; i < 4; i++) { cA[nt][i] = 0.f; cB[nt][i] = 0.f; }

            uint32_t rowoff = (uint32_t)(mt * 16 + lrow) * 256;
            #pragma unroll
            for (int kt = 0; kt < 8; kt++) {
                uint32_t off = rowoff + (uint32_t)(((kt * 2 + qh) ^ rr) * 16);
                uint32_t ahi[4], alo[4];
                asm volatile("ldmatrix.sync.aligned.m8n8.x4.shared.b16 {%0,%1,%2,%3}, [%4];"
                    : "=r"(ahi[0]), "=r"(ahi[1]), "=r"(ahi[2]), "=r"(ahi[3])
                    : "r"(sbase_hi + off));
                asm volatile("ldmatrix.sync.aligned.m8n8.x4.shared.b16 {%0,%1,%2,%3}, [%4];"
                    : "=r"(alo[0]), "=r"(alo[1]), "=r"(alo[2]), "=r"(alo[3])
                    : "r"(sbase_lo + off));
                // load both Wlo fragments up-front (LDS -> mma distance)
                u64 wl0v = *(const u64*)&sm->Wlo[(kt * 512 + fragoff[0]) * 2];
                u64 wl1v = *(const u64*)&sm->Wlo[(kt * 512 + fragoff[1]) * 2];
                mma16816(cA[0], ahi, Whi[0][kt][0], Whi[0][kt][1]);
                mma16816(cA[1], ahi, Whi[1][kt][0], Whi[1][kt][1]);
                mma16816(cB[0], ahi, (uint32_t)wl0v, (uint32_t)(wl0v >> 32));
                mma16816(cB[1], ahi, (uint32_t)wl1v, (uint32_t)(wl1v >> 32));
                mma16816(cB[0], alo, Whi[0][kt][0], Whi[0][kt][1]);
                mma16816(cB[1], alo, Whi[1][kt][0], Whi[1][kt][1]);
            }

            int kbase = mt * 16;
            float cm0 = sm->CM[kbase + g4];
            float cm8 = sm->CM[kbase + 8 + g4];
            int n0i = sm->Idx[kbase + g4];
            int n8i = sm->Idx[kbase + 8 + g4];
            #pragma unroll
            for (int nt = 0; nt < 2; nt++) {
                int coln = nn + nt * 8 + 2 * t4;
                float2 y0 = *(const float2*)&g_ybuf[(size_t)n0i * NF + coln];
                float2 y8 = *(const float2*)&g_ybuf[(size_t)n8i * NF + coln];
                float p0 = cA[nt][0] + cB[nt][0] + b2v[nt].x;
                float p1 = cA[nt][1] + cB[nt][1] + b2v[nt].y;
                float p2 = cA[nt][2] + cB[nt][2] + b2v[nt].x;
                float p3 = cA[nt][3] + cB[nt][3] + b2v[nt].y;
                colacc[nt * 2 + 0] += cm0 * y0.x * p0 + cm8 * y8.x * p2;
                colacc[nt * 2 + 1] += cm0 * y0.y * p1 + cm8 * y8.y * p3;
            }
        }

        #pragma unroll
        for (int m = 4; m <= 16; m <<= 1) {
            #pragma unroll
            for (int i = 0; i < 4; i++)
                colacc[i] += __shfl_xor_sync(0xFFFFFFFF, colacc[i], m);
        }
        if (g4 == 0) {
            *(float2*)&g_acc[(size_t)atom * NF + nn + 2 * t4]     = make_float2(colacc[0], colacc[1]);
            *(float2*)&g_acc[(size_t)atom * NF + nn + 8 + 2 * t4] = make_float2(colacc[2], colacc[3]);
        }
    }
}

// ---------------------------------------------------------------------------
extern "C" void kernel_launch(void* const* d_in, const int* in_sizes, int n_in,
                              void* d_out, int out_size)
{
    const float* x       = (const float*)d_in[0];
    const float* dR      = (const float*)d_in[1];
    const float* dRe     = (const float*)d_in[2];
    const float* pmask   = (const float*)d_in[3];
    const int*   nbr     = (const int*)  d_in[4];
    const float* W1      = (const float*)d_in[5];
    const float* b1      = (const float*)d_in[6];
    const float* W2      = (const float*)d_in[7];
    const float* b2      = (const float*)d_in[8];
    const float* W_in2f  = (const float*)d_in[9];
    const float* W_f2out = (const float*)d_in[10];
    const float* b_f2out = (const float*)d_in[11];
    float* out = (float*)d_out;

    const int SMEM_AC = (16384 + 64 * 128) * 4;   // 98304 B
    const int SMEM_B  = (int)sizeof(SmemB);       // 75328 B

    cudaFuncSetAttribute(gemm128_kernel,      cudaFuncAttributeMaxDynamicSharedMemorySize, SMEM_AC);
    cudaFuncSetAttribute(cfconv_fused_kernel, cudaFuncAttributeMaxDynamicSharedMemorySize, SMEM_B);

    float* ybuf; cudaGetSymbolAddress((void**)&ybuf, g_ybuf);
    float* accb; cudaGetSymbolAddress((void**)&accb, g_acc);

    // A (+ fused W2 prepack in blocks 157..172): y = x @ W_in2f
    gemm128_kernel<<<GRID_GEMM + 16, 256, SMEM_AC>>>(x, W_in2f, nullptr, ybuf, 0, W2);
    // B: fused filter net (FFMA2) + tensor-core GEMM2 + epilogue
    cfconv_fused_kernel<<<NATOMS / APB, 256, SMEM_B>>>(dR, dRe, pmask, nbr, W1, b1, b2);
    // C: out = ssp(acc @ W_f2out + b_f2out)
    gemm128_kernel<<<GRID_GEMM, 256, SMEM_AC>>>(accb, W_f2out, b_f2out, out, 1, nullptr);
    // position-keeper so cfconv sits at overall launch #6 for ncu (-s 5 -c 1)
    dummy_kernel<<<1, 32>>>();
}